// round 2
// baseline (speedup 1.0000x reference)
#include <cuda_runtime.h>

// Problem constants (fixed by the dataset)
#define B   4
#define P   12000
#define NF  64
#define XS  512
#define YS  512
#define GRID_CELLS (XS * YS)              // 262144
#define BP_TOTAL   (B * P)                // 48000
#define OUT_ELEMS  (B * NF * GRID_CELLS)  // 67,108,864 floats = 256 MB
#define QUADS_PER_BATCH (GRID_CELLS / 4)  // 65536

// L2-resident scratch: one slot (64 floats) per potential winning pillar,
// plus a per-(batch,cell) slot map. ~16.3 MB total, fits easily in 126 MB L2.
__device__ float g_scratch[BP_TOTAL * NF];     // 12.3 MB
__device__ int   g_slot[B * GRID_CELLS];       // 4 MB, -1 = untouched

// ---------------------------------------------------------------------------
// Kernel A: reset scratch (0) and slot map (-1). Full-line vectorized stores.
// ---------------------------------------------------------------------------
__global__ void init_kernel() {
    unsigned int i = blockIdx.x * blockDim.x + threadIdx.x;
    // scratch: 3,072,000 floats = 768,000 float4
    if (i < (BP_TOTAL * NF) / 4) {
        ((float4*)g_scratch)[i] = make_float4(0.f, 0.f, 0.f, 0.f);
    }
    // slot map: 1,048,576 ints = 262,144 int4
    if (i < (B * GRID_CELLS) / 4) {
        ((int4*)g_slot)[i] = make_int4(-1, -1, -1, -1);
    }
}

// ---------------------------------------------------------------------------
// Kernel B: slot claim. One thread per (b, pillar). The winning pillar's
// linear index bp becomes the slot id for its cell.
// ---------------------------------------------------------------------------
__global__ void claim_kernel(const int* __restrict__ coord,
                             const int* __restrict__ contains) {
    unsigned int bp = blockIdx.x * blockDim.x + threadIdx.x;
    if (bp >= BP_TOTAL) return;
    if (contains[bp] != 1) return;
    int b = bp / P;
    int y = coord[bp * 3 + 1];
    int x = coord[bp * 3 + 2];
    int idx = b * GRID_CELLS + y * XS + x;
    if (g_slot[idx] == -1)                      // racy pre-filter (cheap)
        atomicCAS(&g_slot[idx], -1, (int)bp);   // winner fixes the slot id
}

// ---------------------------------------------------------------------------
// Kernel C: accumulate. One thread per (b, p, f), f fastest -> pillar loads
// coalesced, scratch atomics contiguous (256B) per pillar, all L2-resident.
// ---------------------------------------------------------------------------
__global__ void accum_kernel(const float* __restrict__ pillars,
                             const int*   __restrict__ coord,
                             const int*   __restrict__ contains) {
    unsigned int t  = blockIdx.x * blockDim.x + threadIdx.x; // [0, B*P*NF)
    unsigned int f  = t & (NF - 1);
    unsigned int bp = t >> 6;
    if (contains[bp] != 1) return;

    float v = pillars[t];
    int b = bp / P;
    int y = coord[bp * 3 + 1];
    int x = coord[bp * 3 + 2];
    int slot = g_slot[b * GRID_CELLS + y * XS + x];  // >= 0, claim done
    atomicAdd(&g_scratch[slot * NF + f], v);
}

// ---------------------------------------------------------------------------
// Kernel D: single streaming write of the 256 MB output.
// One thread per 4-cell quad; loads the quad's 4 slot ids once (int4),
// then writes 64 float4s (one per feature plane). Per feature, a warp writes
// 512 contiguous bytes. Untouched quads (~98%) are a pure zero-store stream.
// ---------------------------------------------------------------------------
__global__ void write_kernel(float* __restrict__ out) {
    unsigned int t = blockIdx.x * blockDim.x + threadIdx.x; // [0, B*65536)
    unsigned int b = t >> 16;
    unsigned int q = t & 0xFFFF;                            // quad within batch

    int4 s = ((const int4*)g_slot)[t];                      // slots for 4 cells
    float4* outq = (float4*)out + ((b * NF) << 16) + q;

    if ((s.x & s.y & s.z & s.w) == -1) {
        // all four cells untouched: stream zeros
        float4 z = make_float4(0.f, 0.f, 0.f, 0.f);
        #pragma unroll
        for (int f = 0; f < NF; ++f)
            outq[(unsigned)f << 16] = z;
    } else {
        #pragma unroll 8
        for (int f = 0; f < NF; ++f) {
            float4 v;
            v.x = (s.x >= 0) ? g_scratch[s.x * NF + f] : 0.f;
            v.y = (s.y >= 0) ? g_scratch[s.y * NF + f] : 0.f;
            v.z = (s.z >= 0) ? g_scratch[s.z * NF + f] : 0.f;
            v.w = (s.w >= 0) ? g_scratch[s.w * NF + f] : 0.f;
            outq[(unsigned)f << 16] = v;
        }
    }
}

extern "C" void kernel_launch(void* const* d_in, const int* in_sizes, int n_in,
                              void* d_out, int out_size) {
    const float* pillars  = (const float*)d_in[0];  // [B, P, NF] fp32
    const int*   coord    = (const int*)  d_in[1];  // [B, P, 3]  int32
    const int*   contains = (const int*)  d_in[2];  // [B, P]     int32
    float*       out      = (float*)d_out;          // [B, NF, XS, YS] fp32

    // A: reset slot map + scratch (16 MB, L2-resident afterwards)
    {
        const int threads = 256;
        const int work = (BP_TOTAL * NF) / 4;       // 768000 (the larger range)
        const int blocks = (work + threads - 1) / threads;
        init_kernel<<<blocks, threads>>>();
    }
    // B: claim slots (48000 threads)
    {
        const int threads = 256;
        const int blocks = (BP_TOTAL + threads - 1) / threads;
        claim_kernel<<<blocks, threads>>>(coord, contains);
    }
    // C: accumulate into L2-resident scratch (3.07M threads)
    {
        const int threads = 256;
        const int blocks = (B * P * NF) / threads;  // 12000, exact
        accum_kernel<<<blocks, threads>>>(pillars, coord, contains);
    }
    // D: single streaming 256 MB output write (262144 threads)
    {
        const int threads = 256;
        const int blocks = (B * QUADS_PER_BATCH) / threads; // 1024, exact
        write_kernel<<<blocks, threads>>>(out);
    }
}

// round 3
// speedup vs baseline: 1.2369x; 1.2369x over previous
#include <cuda_runtime.h>

// Problem constants (fixed by the dataset)
#define B   4
#define P   12000
#define NF  64
#define XS  512
#define YS  512
#define GRID_CELLS (XS * YS)              // 262144
#define BP_TOTAL   (B * P)                // 48000
#define TILE_CELLS 1024                   // cells per write-kernel block
#define TILES_PER_BATCH (GRID_CELLS / TILE_CELLS)   // 256

// L2-resident scratch: one 64-float slot per potential winning pillar,
// plus a per-(batch,cell) slot map. ~16.3 MB total (L2 = 126 MB).
__device__ float g_scratch[BP_TOTAL * NF];     // 12.3 MB
__device__ int   g_slot[B * GRID_CELLS];       // 4 MB, -1 = untouched

// ---------------------------------------------------------------------------
// Kernel A: reset scratch (0) and slot map (-1).
// ---------------------------------------------------------------------------
__global__ void init_kernel() {
    unsigned int i = blockIdx.x * blockDim.x + threadIdx.x;
    if (i < (BP_TOTAL * NF) / 4)
        ((float4*)g_scratch)[i] = make_float4(0.f, 0.f, 0.f, 0.f);
    if (i < (B * GRID_CELLS) / 4)
        ((int4*)g_slot)[i] = make_int4(-1, -1, -1, -1);
}

// ---------------------------------------------------------------------------
// Kernel B: slot claim. Winning pillar's linear index becomes the cell's slot.
// ---------------------------------------------------------------------------
__global__ void claim_kernel(const int* __restrict__ coord,
                             const int* __restrict__ contains) {
    unsigned int bp = blockIdx.x * blockDim.x + threadIdx.x;
    if (bp >= BP_TOTAL) return;
    if (contains[bp] != 1) return;
    int b = bp / P;
    int y = coord[bp * 3 + 1];
    int x = coord[bp * 3 + 2];
    int idx = b * GRID_CELLS + y * XS + x;
    if (g_slot[idx] == -1)
        atomicCAS(&g_slot[idx], -1, (int)bp);
}

// ---------------------------------------------------------------------------
// Kernel C: accumulate into L2-resident scratch. Thread per (b,p,f).
// ---------------------------------------------------------------------------
__global__ void accum_kernel(const float* __restrict__ pillars,
                             const int*   __restrict__ coord,
                             const int*   __restrict__ contains) {
    unsigned int t  = blockIdx.x * blockDim.x + threadIdx.x;
    unsigned int f  = t & (NF - 1);
    unsigned int bp = t >> 6;
    if (contains[bp] != 1) return;

    float v = pillars[t];
    int b = bp / P;
    int y = coord[bp * 3 + 1];
    int x = coord[bp * 3 + 2];
    int slot = g_slot[b * GRID_CELLS + y * XS + x];
    atomicAdd(&g_scratch[slot * NF + f], v);
}

// ---------------------------------------------------------------------------
// Kernel D: fused zero + overwrite. Block = one 1024-cell tile of one batch.
//   Phase 1: load the tile's 256 int4 slot entries, compact touched cells
//            into shared memory (expected ~23 per tile).
//   Phase 2: unconditionally zero tile x 64 features (uniform STG.128 stream,
//            zero divergence -> full store bandwidth).
//   Phase 3: overwrite touched (cell, f) from scratch. Scratch reads are
//            coalesced 256B rows; scattered output stores merge in L2 on
//            lines this block just wrote.
// ---------------------------------------------------------------------------
__global__ void write_kernel(float* __restrict__ out) {
    __shared__ int s_cell[TILE_CELLS];
    __shared__ int s_slotid[TILE_CELLS];
    __shared__ int s_n;

    const unsigned tid  = threadIdx.x;            // 0..255
    const unsigned T    = blockIdx.x;             // 0..1023
    const unsigned b    = T >> 8;                 // batch
    const unsigned tile = T & 255;                // tile within batch

    if (tid == 0) s_n = 0;
    __syncthreads();

    // Phase 1: slot compaction
    const unsigned qidx = (b << 16) + (tile << 8) + tid;  // int4 index
    int4 s4 = ((const int4*)g_slot)[qidx];
    int sl[4] = {s4.x, s4.y, s4.z, s4.w};
    #pragma unroll
    for (int k = 0; k < 4; ++k) {
        if (sl[k] >= 0) {
            int p = atomicAdd(&s_n, 1);
            s_cell[p]   = (int)(tid * 4 + k);
            s_slotid[p] = sl[k];
        }
    }
    __syncthreads();
    const int n = s_n;

    // Phase 2: unconditional zero stream (uniform for every warp)
    float4* base = (float4*)out + ((b * NF) << 16) + (tile << 8) + tid;
    const float4 z = make_float4(0.f, 0.f, 0.f, 0.f);
    #pragma unroll
    for (unsigned f = 0; f < NF; ++f)
        base[f << 16] = z;
    __syncthreads();   // order phase-2 stores before phase-3 overwrites

    // Phase 3: overwrite touched cells
    const unsigned total = (unsigned)n << 6;      // n * 64
    const unsigned cell_base = (tile << 10);      // scalar cell offset in batch
    for (unsigned i = tid; i < total; i += 256) {
        unsigned ci = i >> 6;
        unsigned f  = i & 63;
        float v = g_scratch[(unsigned)s_slotid[ci] * NF + f];
        out[((b * NF + f) << 18) + cell_base + (unsigned)s_cell[ci]] = v;
    }
}

extern "C" void kernel_launch(void* const* d_in, const int* in_sizes, int n_in,
                              void* d_out, int out_size) {
    const float* pillars  = (const float*)d_in[0];  // [B, P, NF] fp32
    const int*   coord    = (const int*)  d_in[1];  // [B, P, 3]  int32
    const int*   contains = (const int*)  d_in[2];  // [B, P]     int32
    float*       out      = (float*)d_out;          // [B, NF, XS, YS] fp32

    {   // A: reset scratch + slot map
        const int threads = 256;
        const int work = (BP_TOTAL * NF) / 4;       // 768000
        init_kernel<<<(work + threads - 1) / threads, threads>>>();
    }
    {   // B: claim slots
        const int threads = 256;
        claim_kernel<<<(BP_TOTAL + threads - 1) / threads, threads>>>(coord, contains);
    }
    {   // C: accumulate
        const int threads = 256;
        accum_kernel<<<(B * P * NF) / threads, threads>>>(pillars, coord, contains);
    }
    {   // D: fused zero + overwrite (1024 blocks x 256 threads)
        write_kernel<<<B * TILES_PER_BATCH, 256>>>(out);
    }
}

// round 4
// speedup vs baseline: 1.2406x; 1.0030x over previous
#include <cuda_runtime.h>

// Problem constants (fixed by the dataset)
#define B   4
#define P   12000
#define NF  64
#define XS  512
#define YS  512
#define GRID_CELLS (XS * YS)              // 262144
#define BP_TOTAL   (B * P)                // 48000
#define OUT_ELEMS  (B * NF * GRID_CELLS)  // 67,108,864 floats = 256 MB
#define TILE_CELLS 1024
#define TILES_PER_BATCH (GRID_CELLS / TILE_CELLS)   // 256

// Per-(batch,cell) chain head (-1 = untouched) and per-pillar next pointer.
__device__ int g_slot[B * GRID_CELLS];    // 4 MB
__device__ int g_next[BP_TOTAL];          // 192 KB (no init needed)

// ---------------------------------------------------------------------------
// Kernel A: reset slot map to -1.
// ---------------------------------------------------------------------------
__global__ void init_kernel() {
    unsigned int i = blockIdx.x * blockDim.x + threadIdx.x;
    ((int4*)g_slot)[i] = make_int4(-1, -1, -1, -1);   // exact grid, no guard
}

// ---------------------------------------------------------------------------
// Kernel B: build per-cell pillar chains. One atomicExch per valid pillar.
// ---------------------------------------------------------------------------
__global__ void claim_kernel(const int* __restrict__ coord,
                             const int* __restrict__ contains) {
    unsigned int bp = blockIdx.x * blockDim.x + threadIdx.x;
    if (bp >= BP_TOTAL) return;
    if (contains[bp] != 1) return;
    int b = bp / P;
    int y = coord[bp * 3 + 1];
    int x = coord[bp * 3 + 2];
    int idx = b * GRID_CELLS + y * XS + x;
    int prev = atomicExch(&g_slot[idx], (int)bp);
    g_next[bp] = prev;
}

// ---------------------------------------------------------------------------
// Kernel C: pure zero stream of the 256 MB output (proven 5.7 TB/s config).
// ---------------------------------------------------------------------------
__global__ void zero_out_kernel(float4* __restrict__ out) {
    unsigned int i = blockIdx.x * blockDim.x + threadIdx.x;
    out[i] = make_float4(0.f, 0.f, 0.f, 0.f);
}

// ---------------------------------------------------------------------------
// Kernel D: overwrite touched cells only.
//   Phase 1: block = one 1024-cell tile; compact touched cells into smem.
//   Phase 2: 64 threads per touched cell; each thread owns one feature f,
//            walks the cell's pillar chain (uniform branch across the
//            64 threads, chain length ~1) summing pillars[p*64+f]
//            (coalesced 256B reads), then one 4B store to the output.
// ---------------------------------------------------------------------------
__global__ void overwrite_kernel(const float* __restrict__ pillars,
                                 float* __restrict__ out) {
    __shared__ int s_cell[TILE_CELLS];
    __shared__ int s_head[TILE_CELLS];
    __shared__ int s_n;

    const unsigned tid  = threadIdx.x;            // 0..255
    const unsigned T    = blockIdx.x;             // 0..1023
    const unsigned b    = T >> 8;
    const unsigned tile = T & 255;

    if (tid == 0) s_n = 0;
    __syncthreads();

    // Phase 1: compact touched cells of this tile
    const unsigned qidx = (b << 16) + (tile << 8) + tid;   // int4 index
    int4 s4 = ((const int4*)g_slot)[qidx];
    int sl[4] = {s4.x, s4.y, s4.z, s4.w};
    #pragma unroll
    for (int k = 0; k < 4; ++k) {
        if (sl[k] >= 0) {
            int p = atomicAdd(&s_n, 1);
            s_cell[p] = (int)(tid * 4 + k);
            s_head[p] = sl[k];
        }
    }
    __syncthreads();
    const int n = s_n;

    // Phase 2: chain-walk gather + scattered store
    const unsigned total = (unsigned)n << 6;      // n * 64
    const unsigned cell_base = (tile << 10);
    for (unsigned i = tid; i < total; i += 256) {
        unsigned ci = i >> 6;
        unsigned f  = i & 63;
        int p = s_head[ci];
        float acc = 0.f;
        while (p >= 0) {                          // uniform across the 64 lanes
            acc += pillars[(unsigned)p * NF + f]; // coalesced 256B row read
            p = g_next[p];                        // broadcast load
        }
        out[((b * NF + f) << 18) + cell_base + (unsigned)s_cell[ci]] = acc;
    }
}

extern "C" void kernel_launch(void* const* d_in, const int* in_sizes, int n_in,
                              void* d_out, int out_size) {
    const float* pillars  = (const float*)d_in[0];  // [B, P, NF] fp32
    const int*   coord    = (const int*)  d_in[1];  // [B, P, 3]  int32
    const int*   contains = (const int*)  d_in[2];  // [B, P]     int32
    float*       out      = (float*)d_out;          // [B, NF, XS, YS] fp32

    {   // A: reset slot map (262144 int4 stores, exact grid)
        const int threads = 256;
        const int blocks  = (B * GRID_CELLS / 4) / threads;   // 1024
        init_kernel<<<blocks, threads>>>();
    }
    {   // B: build chains (48000 threads)
        const int threads = 256;
        claim_kernel<<<(BP_TOTAL + threads - 1) / threads, threads>>>(coord, contains);
    }
    {   // C: zero 256 MB output (proven config: 65536 x 256)
        const int threads = 256;
        const int blocks  = (OUT_ELEMS / 4) / threads;        // 65536
        zero_out_kernel<<<blocks, threads>>>((float4*)out);
    }
    {   // D: overwrite touched cells (1024 blocks x 256 threads)
        overwrite_kernel<<<B * TILES_PER_BATCH, 256>>>(pillars, out);
    }
}

// round 5
// speedup vs baseline: 1.7251x; 1.3905x over previous
#include <cuda_runtime.h>

// Problem constants (fixed by the dataset)
#define B   4
#define P   12000
#define NF  64
#define XS  512
#define YS  512
#define GRID_CELLS (GRID_W * GRID_W)
#define GRID_W 512
#define CELLS  (XS * YS)                  // 262144 per batch
#define QUADS  (CELLS / 4)                // 65536 per batch
#define BP_TOTAL (B * P)                  // 48000
#define HALF_F 32                         // features per block (64 split 2 ways)

// Per-(batch,cell) chain head (-1 = untouched) and per-pillar next pointer.
__device__ int g_slot[B * CELLS];         // 4 MB
__device__ int g_next[BP_TOTAL];          // 192 KB (written before read, no init)

// ---------------------------------------------------------------------------
// Kernel A: reset slot map to -1. Exact grid, no guard.
// ---------------------------------------------------------------------------
__global__ void init_kernel() {
    unsigned int i = blockIdx.x * blockDim.x + threadIdx.x;
    ((int4*)g_slot)[i] = make_int4(-1, -1, -1, -1);
}

// ---------------------------------------------------------------------------
// Kernel B: build per-cell pillar chains. One atomicExch per valid pillar.
// ---------------------------------------------------------------------------
__global__ void claim_kernel(const int* __restrict__ coord,
                             const int* __restrict__ contains) {
    unsigned int bp = blockIdx.x * blockDim.x + threadIdx.x;
    if (bp >= BP_TOTAL) return;
    if (contains[bp] != 1) return;
    int b = bp / P;
    int y = coord[bp * 3 + 1];
    int x = coord[bp * 3 + 2];
    int idx = b * CELLS + y * XS + x;
    int prev = atomicExch(&g_slot[idx], (int)bp);
    g_next[bp] = prev;
}

// ---------------------------------------------------------------------------
// Kernel C: fused zero + overwrite, barrier-free.
// Block = (batch, feature-half, 256-quad tile). 256 threads, 8 warps.
//   Step 1: thread loads its quad's int4 slot entry (miss latency hides
//           behind the store stream below — no dependency).
//   Step 2: unconditional zero of quad x 32 planes (uniform STG.128 stream).
//   Step 3: __syncwarp, then warp-cooperative overwrite of touched cells:
//           ballot over the warp's 128 cells; per touched cell, lane=feature
//           -> coalesced 128B pillar read, uniform chain walk, one 4B store
//           to a line this warp just wrote (L2-resident).
// ---------------------------------------------------------------------------
__global__ void fused_kernel(const float* __restrict__ pillars,
                             float* __restrict__ out) {
    const unsigned tid  = threadIdx.x;             // 0..255
    const unsigned lane = tid & 31;
    const unsigned blk  = blockIdx.x;              // 0..2047
    const unsigned b    = blk >> 9;                // batch
    const unsigned half = (blk >> 8) & 1;          // feature half
    const unsigned tile = blk & 255;               // 256-quad tile

    const unsigned q = (tile << 8) + tid;          // quad index within batch

    // Step 1: slot load (independent of the stores below)
    int4 s4 = ((const int4*)g_slot)[(b << 16) + q];
    int sl[4] = {s4.x, s4.y, s4.z, s4.w};

    // Step 2: unconditional zero stream, 32 planes
    float4* base = (float4*)out + (((b * NF + half * HALF_F)) << 16) + q;
    const float4 z = make_float4(0.f, 0.f, 0.f, 0.f);
    #pragma unroll
    for (unsigned j = 0; j < HALF_F; ++j)
        base[j << 16] = z;

    __syncwarp();   // order zero-stores across the warp before overwrites

    // Step 3: warp-cooperative overwrite
    const unsigned f = half * HALF_F + lane;       // this lane's feature
    #pragma unroll
    for (int k = 0; k < 4; ++k) {
        unsigned m = __ballot_sync(0xFFFFFFFFu, sl[k] >= 0);
        while (m) {
            int src = __ffs(m) - 1;
            m &= m - 1;
            int p = __shfl_sync(0xFFFFFFFFu, sl[k], src);
            unsigned cell = (__shfl_sync(0xFFFFFFFFu, q, src) << 2) + k;
            float acc = 0.f;
            while (p >= 0) {                       // uniform across the warp
                acc += pillars[(unsigned)p * NF + f];  // coalesced 128B row
                p = g_next[p];                     // broadcast load
            }
            out[((b * NF + f) << 18) + cell] = acc;
        }
    }
}

extern "C" void kernel_launch(void* const* d_in, const int* in_sizes, int n_in,
                              void* d_out, int out_size) {
    const float* pillars  = (const float*)d_in[0];  // [B, P, NF] fp32
    const int*   coord    = (const int*)  d_in[1];  // [B, P, 3]  int32
    const int*   contains = (const int*)  d_in[2];  // [B, P]     int32
    float*       out      = (float*)d_out;          // [B, NF, XS, YS] fp32

    {   // A: reset slot map (262144 int4 stores)
        const int threads = 256;
        const int blocks  = (B * CELLS / 4) / threads;   // 1024
        init_kernel<<<blocks, threads>>>();
    }
    {   // B: build chains (48000 threads)
        const int threads = 256;
        claim_kernel<<<(BP_TOTAL + threads - 1) / threads, threads>>>(coord, contains);
    }
    {   // C: fused zero + overwrite (2048 blocks x 256 threads)
        fused_kernel<<<B * 2 * 256, 256>>>(pillars, out);
    }
}